// round 6
// baseline (speedup 1.0000x reference)
#include <cuda_runtime.h>
#include <cstdint>

// Shapes (compile-time constants)
#define BB 8
#define SS 1024
#define DD 512
#define HH 8
#define HD 64
#define DFF 2048
#define MTOK (BB*SS)   // 8192

typedef long long ll;

// ---------------- scratch (device globals: allocation-guard safe) -----------
__device__ float g_h  [MTOK*DD];        // rmsnorm1 output
__device__ float g_q  [MTOK*DD];
__device__ float g_k  [MTOK*DD];
__device__ float g_v  [MTOK*DD];
__device__ float g_ctx[MTOK*DD];
__device__ float g_y  [MTOK*DD];        // residual after attention
__device__ float g_h2 [MTOK*DD];        // rmsnorm2 output
__device__ float g_ff [MTOK*DFF];       // relu(ffn1)

// ---------------- helpers ----------------------------------------------------
__device__ __forceinline__ float ftf32(float x) {
    uint32_t o, i = __float_as_uint(x);
    asm("cvt.rna.tf32.f32 %0, %1;" : "=r"(o) : "r"(i));
    return __uint_as_float(o);
}
__device__ __forceinline__ void mma_tf32(float c[4], const uint32_t a[4], const uint32_t b[2]) {
    asm volatile(
        "mma.sync.aligned.m16n8k8.row.col.f32.tf32.tf32.f32 "
        "{%0,%1,%2,%3}, {%4,%5,%6,%7}, {%8,%9}, {%0,%1,%2,%3};\n"
        : "+f"(c[0]), "+f"(c[1]), "+f"(c[2]), "+f"(c[3])
        : "r"(a[0]), "r"(a[1]), "r"(a[2]), "r"(a[3]), "r"(b[0]), "r"(b[1]));
}

#define CP_ASYNC16(dst, src) \
    asm volatile("cp.async.cg.shared.global [%0], [%1], 16;\n" :: "r"(dst), "l"(src))
#define CP_COMMIT() asm volatile("cp.async.commit_group;\n" ::: "memory")
#define CP_WAIT(n)  asm volatile("cp.async.wait_group %0;\n" :: "n"(n) : "memory")

__device__ __forceinline__ uint32_t smem_u32(const void* p) {
    uint32_t a;
    asm("{ .reg .u64 t; cvta.to.shared.u64 t, %1; cvt.u32.u64 %0, t; }"
        : "=r"(a) : "l"(p));
    return a;
}

// ---------------- RMSNorm: one block (128 thr) per row of 512 ----------------
__global__ __launch_bounds__(128) void rmsnorm_kernel(
    const float* __restrict__ x, const float* __restrict__ w,
    float* __restrict__ out)
{
    const int row = blockIdx.x;
    const int t = threadIdx.x;
    const float4 v = ((const float4*)(x + (ll)row*DD))[t];
    float ss = v.x*v.x + v.y*v.y + v.z*v.z + v.w*v.w;
    #pragma unroll
    for (int o = 16; o; o >>= 1) ss += __shfl_xor_sync(0xFFFFFFFFu, ss, o);
    __shared__ float wsum[4];
    if ((t & 31) == 0) wsum[t >> 5] = ss;
    __syncthreads();
    const float tot = wsum[0] + wsum[1] + wsum[2] + wsum[3];
    const float r = rsqrtf(tot * (1.0f/DD) + 1e-6f);
    const float4 wv = ((const float4*)w)[t];
    float4 o4;
    o4.x = v.x * r * wv.x; o4.y = v.y * r * wv.y;
    o4.z = v.z * r * wv.z; o4.w = v.w * r * wv.w;
    ((float4*)(out + (ll)row*DD))[t] = o4;
}

// ---------------- TF32 mma.sync GEMM, 64x32 warp tiles, 8 warps --------------
// C[m,n] = sum_k A[m,k]*B[n,k]  (both K-major / NT).
// 128x128 block, 256 threads (8 warps, 2x4), warp tile 64x32, BK=16,
// 3-stage cp.async pipeline, raw-f32 operands (HW tf32 truncation).
// EPI: 0=none, 1=relu, 2=+Add.  NMAT=3: fused QKV (B/C selected by blockIdx.z).
#define STG   3
#define PAD   20                    // floats per smem row (16 + 4)
#define ATILF (128*PAD)             // 2560 floats per operand tile
#define STGF  (2*ATILF)             // floats per stage
#define GSMEM (STG*STGF*4)          // 61440 B

template<int EPI, int NMAT>
__global__ __launch_bounds__(256, 2) void gemm_tc3(
    const float* __restrict__ A,
    const float* __restrict__ B0, const float* __restrict__ B1,
    const float* __restrict__ B2,
    const float* __restrict__ Add,
    float* __restrict__ C0, float* __restrict__ C1, float* __restrict__ C2,
    int K, int N)
{
    extern __shared__ float dsm[];

    const float* B = B0;
    float*       C = C0;
    if (NMAT == 3) {
        if (blockIdx.z == 1) { B = B1; C = C1; }
        else if (blockIdx.z == 2) { B = B2; C = C2; }
    }

    const int tid  = threadIdx.x;
    const int warp = tid >> 5, lane = tid & 31;
    const int wm   = warp >> 2, wn = warp & 3;      // 2x4 warp grid
    const int gid  = lane >> 2, tig = lane & 3;
    const int m0   = blockIdx.y * 128;
    const int n0   = blockIdx.x * 128;

    const uint32_t smb = smem_u32(dsm);
    const float* Ab = A + (ll)m0 * K;
    const float* Bb = B + (ll)n0 * K;

    float acc[4][4][4];
    #pragma unroll
    for (int mt = 0; mt < 4; ++mt)
        #pragma unroll
        for (int nt = 0; nt < 4; ++nt)
            #pragma unroll
            for (int i = 0; i < 4; ++i) acc[mt][nt][i] = 0.f;

    // stage j -> buffer j%STG. Each thread copies 2x16B of A and of B.
    auto issue = [&](int j) {
        const int st = j % STG;
        const int k0 = j * 16;
        const uint32_t ab = smb + st*STGF*4;
        const uint32_t bb = ab + ATILF*4;
        #pragma unroll
        for (int i = 0; i < 2; ++i) {
            const int id = tid + i*256;
            const int r = id >> 2, c = id & 3;
            CP_ASYNC16(ab + (r*PAD + c*4)*4, Ab + (ll)r*K + k0 + c*4);
            CP_ASYNC16(bb + (r*PAD + c*4)*4, Bb + (ll)r*K + k0 + c*4);
        }
        CP_COMMIT();
    };

    const int NC = K / 16;
    issue(0); issue(1); issue(2);

    for (int j = 0; j < NC; ++j) {
        CP_WAIT(STG-1);
        __syncthreads();

        const int stF = (j % STG)*STGF;
        const float* As = dsm + stF;
        const float* Bs = dsm + stF + ATILF;

        #pragma unroll
        for (int ks = 0; ks < 2; ++ks) {
            const int k = ks*8 + tig;
            uint32_t af[4][4], bf[4][2];
            #pragma unroll
            for (int mt = 0; mt < 4; ++mt) {
                const int r = (wm*64 + mt*16 + gid)*PAD + k;
                af[mt][0] = __float_as_uint(As[r]);
                af[mt][1] = __float_as_uint(As[r + 8*PAD]);
                af[mt][2] = __float_as_uint(As[r + 4]);
                af[mt][3] = __float_as_uint(As[r + 8*PAD + 4]);
            }
            #pragma unroll
            for (int nt = 0; nt < 4; ++nt) {
                const int r = (wn*32 + nt*8 + gid)*PAD + k;
                bf[nt][0] = __float_as_uint(Bs[r]);
                bf[nt][1] = __float_as_uint(Bs[r + 4]);
            }
            #pragma unroll
            for (int mt = 0; mt < 4; ++mt)
                #pragma unroll
                for (int nt = 0; nt < 4; ++nt)
                    mma_tf32(acc[mt][nt], af[mt], bf[nt]);
        }

        __syncthreads();
        if (j + STG < NC) issue(j + STG);
    }

    // ---- epilogue
    #pragma unroll
    for (int mt = 0; mt < 4; ++mt) {
        #pragma unroll
        for (int nt = 0; nt < 4; ++nt) {
            const int col = n0 + wn*32 + nt*8 + tig*2;
            #pragma unroll
            for (int h = 0; h < 2; ++h) {
                const ll row = (ll)(m0 + wm*64 + mt*16 + gid + h*8);
                float2 v;
                v.x = acc[mt][nt][h*2+0];
                v.y = acc[mt][nt][h*2+1];
                if (EPI == 1) { v.x = fmaxf(v.x, 0.f); v.y = fmaxf(v.y, 0.f); }
                if (EPI == 2) {
                    const float2 ad = *(const float2*)(Add + row*N + col);
                    v.x += ad.x; v.y += ad.y;
                }
                *(float2*)(C + row*N + col) = v;
            }
        }
    }
}

// ---------------- Fused flash attention (unchanged, passing) -----------------
#define FQ 128
#define FK 64
#define FLDS 68   // 64 + 4 pad

struct FlashS {
    float stage[FQ][FLDS];
    float ks[FK][FLDS];
    float vs[HD][FLDS];
};

__global__ __launch_bounds__(256) void flash_attn(
    const float* __restrict__ Q, const float* __restrict__ Kg,
    const float* __restrict__ Vg, const float* __restrict__ Bias,
    float* __restrict__ Ctx)
{
    extern __shared__ char smraw[];
    FlashS& sm = *reinterpret_cast<FlashS*>(smraw);

    const int z  = blockIdx.y;
    const int b  = z >> 3, hh = z & 7;
    const int q0 = blockIdx.x * FQ;
    const ll off = (ll)b*SS*DD + (ll)hh*HD;
    const float* Qz = Q  + off;
    const float* Kz = Kg + off;
    const float* Vz = Vg + off;
    const float* Bz = Bias + ((ll)z*SS + q0)*SS;
    float*       Cz = Ctx + off;

    const int tid = threadIdx.x, warp = tid >> 5, lane = tid & 31;
    const int gid = lane >> 2, tig = lane & 3;
    const int wrow = warp * 16;

    #pragma unroll
    for (int i = 0; i < 8; ++i) {
        const int idx = tid + i*256;
        const int r = idx >> 4, c = (idx & 15) << 2;
        float4 v = *(const float4*)(Qz + (ll)(q0 + r)*DD + c);
        v.x = ftf32(v.x); v.y = ftf32(v.y); v.z = ftf32(v.z); v.w = ftf32(v.w);
        *(float4*)&sm.stage[r][c] = v;
    }
    __syncthreads();
    uint32_t qf[8][4];
    #pragma unroll
    for (int kc = 0; kc < 8; ++kc) {
        const int k = kc*8 + tig;
        qf[kc][0] = __float_as_uint(sm.stage[wrow+gid  ][k  ]);
        qf[kc][1] = __float_as_uint(sm.stage[wrow+gid+8][k  ]);
        qf[kc][2] = __float_as_uint(sm.stage[wrow+gid  ][k+4]);
        qf[kc][3] = __float_as_uint(sm.stage[wrow+gid+8][k+4]);
    }
    __syncthreads();

    float oacc[8][4];
    #pragma unroll
    for (int nt = 0; nt < 8; ++nt)
        #pragma unroll
        for (int i = 0; i < 4; ++i) oacc[nt][i] = 0.f;
    float m0v = -1e30f, m1v = -1e30f, l0 = 0.f, l1 = 0.f;

    for (int j = 0; j < SS/FK; ++j) {
        #pragma unroll
        for (int i = 0; i < 4; ++i) {
            const int idx = tid + i*256;
            const int r = idx >> 4, c = (idx & 15) << 2;
            float4 kv = *(const float4*)(Kz + (ll)(j*FK + r)*DD + c);
            kv.x = ftf32(kv.x); kv.y = ftf32(kv.y); kv.z = ftf32(kv.z); kv.w = ftf32(kv.w);
            *(float4*)&sm.ks[r][c] = kv;
            float4 vv = *(const float4*)(Vz + (ll)(j*FK + r)*DD + c);
            vv.x = ftf32(vv.x); vv.y = ftf32(vv.y); vv.z = ftf32(vv.z); vv.w = ftf32(vv.w);
            sm.vs[c+0][r] = vv.x; sm.vs[c+1][r] = vv.y;
            sm.vs[c+2][r] = vv.z; sm.vs[c+3][r] = vv.w;
        }
        __syncthreads();

        float sacc[8][4];
        #pragma unroll
        for (int nt = 0; nt < 8; ++nt)
            #pragma unroll
            for (int i = 0; i < 4; ++i) sacc[nt][i] = 0.f;
        #pragma unroll
        for (int kc = 0; kc < 8; ++kc) {
            const int k = kc*8 + tig;
            #pragma unroll
            for (int nt = 0; nt < 8; ++nt) {
                const int cc = nt*8 + gid;
                uint32_t bf[2];
                bf[0] = __float_as_uint(sm.ks[cc][k  ]);
                bf[1] = __float_as_uint(sm.ks[cc][k+4]);
                mma_tf32(sacc[nt], qf[kc], bf);
            }
        }

        float mx0 = -1e30f, mx1 = -1e30f;
        const float* br0 = Bz + (ll)(wrow+gid  )*SS + j*FK + 2*tig;
        const float* br1 = Bz + (ll)(wrow+gid+8)*SS + j*FK + 2*tig;
        #pragma unroll
        for (int nt = 0; nt < 8; ++nt) {
            const float2 b0 = *(const float2*)(br0 + nt*8);
            const float2 b1 = *(const float2*)(br1 + nt*8);
            sacc[nt][0] += b0.x; sacc[nt][1] += b0.y;
            sacc[nt][2] += b1.x; sacc[nt][3] += b1.y;
            mx0 = fmaxf(mx0, fmaxf(sacc[nt][0], sacc[nt][1]));
            mx1 = fmaxf(mx1, fmaxf(sacc[nt][2], sacc[nt][3]));
        }
        #pragma unroll
        for (int o = 1; o <= 2; o <<= 1) {
            mx0 = fmaxf(mx0, __shfl_xor_sync(0xFFFFFFFFu, mx0, o));
            mx1 = fmaxf(mx1, __shfl_xor_sync(0xFFFFFFFFu, mx1, o));
        }
        const float mn0 = fmaxf(m0v, mx0), mn1 = fmaxf(m1v, mx1);
        const float sc0 = __expf(m0v - mn0), sc1 = __expf(m1v - mn1);
        m0v = mn0; m1v = mn1;

        float rs0 = 0.f, rs1 = 0.f;
        #pragma unroll
        for (int nt = 0; nt < 8; ++nt) {
            const float p0 = __expf(sacc[nt][0] - mn0);
            const float p1 = __expf(sacc[nt][1] - mn0);
            const float p2 = __expf(sacc[nt][2] - mn1);
            const float p3 = __expf(sacc[nt][3] - mn1);
            rs0 += p0 + p1; rs1 += p2 + p3;
            float2 w0; w0.x = ftf32(p0); w0.y = ftf32(p1);
            float2 w1; w1.x = ftf32(p2); w1.y = ftf32(p3);
            *(float2*)&sm.stage[wrow+gid  ][nt*8 + 2*tig] = w0;
            *(float2*)&sm.stage[wrow+gid+8][nt*8 + 2*tig] = w1;
        }
        #pragma unroll
        for (int o = 1; o <= 2; o <<= 1) {
            rs0 += __shfl_xor_sync(0xFFFFFFFFu, rs0, o);
            rs1 += __shfl_xor_sync(0xFFFFFFFFu, rs1, o);
        }
        l0 = l0*sc0 + rs0;
        l1 = l1*sc1 + rs1;
        #pragma unroll
        for (int nt = 0; nt < 8; ++nt) {
            oacc[nt][0] *= sc0; oacc[nt][1] *= sc0;
            oacc[nt][2] *= sc1; oacc[nt][3] *= sc1;
        }
        __syncwarp();

        #pragma unroll
        for (int kc = 0; kc < 8; ++kc) {
            const int k = kc*8 + tig;
            uint32_t af[4];
            af[0] = __float_as_uint(sm.stage[wrow+gid  ][k  ]);
            af[1] = __float_as_uint(sm.stage[wrow+gid+8][k  ]);
            af[2] = __float_as_uint(sm.stage[wrow+gid  ][k+4]);
            af[3] = __float_as_uint(sm.stage[wrow+gid+8][k+4]);
            #pragma unroll
            for (int nt = 0; nt < 8; ++nt) {
                const int cc = nt*8 + gid;
                uint32_t bf[2];
                bf[0] = __float_as_uint(sm.vs[cc][k  ]);
                bf[1] = __float_as_uint(sm.vs[cc][k+4]);
                mma_tf32(oacc[nt], af, bf);
            }
        }
        __syncthreads();
    }

    const float inv0 = 1.f / l0, inv1 = 1.f / l1;
    #pragma unroll
    for (int nt = 0; nt < 8; ++nt) {
        const int col = nt*8 + 2*tig;
        float2 w0; w0.x = oacc[nt][0]*inv0; w0.y = oacc[nt][1]*inv0;
        float2 w1; w1.x = oacc[nt][2]*inv1; w1.y = oacc[nt][3]*inv1;
        *(float2*)(Cz + (ll)(q0 + wrow + gid    )*DD + col) = w0;
        *(float2*)(Cz + (ll)(q0 + wrow + gid + 8)*DD + col) = w1;
    }
}

// ---------------- host orchestration -----------------------------------------
extern "C" void kernel_launch(void* const* d_in, const int* in_sizes, int n_in,
                              void* d_out, int out_size)
{
    const float* Wk   = (const float*)d_in[0]; // primals_1
    const float* Wo   = (const float*)d_in[1]; // primals_2
    const float* Wq   = (const float*)d_in[2]; // primals_3
    const float* Wv   = (const float*)d_in[3]; // primals_4
    const float* G1   = (const float*)d_in[4]; // primals_5
    const float* Wi   = (const float*)d_in[5]; // primals_6 [DFF,D]
    const float* Wo2  = (const float*)d_in[6]; // primals_7 [D,DFF]
    const float* G2   = (const float*)d_in[7]; // primals_8
    const float* X    = (const float*)d_in[8]; // primals_9 [B,S,D]
    const float* Bias = (const float*)d_in[9]; // primals_10 [B,H,S,S]
    float* Out = (float*)d_out;

    float *h, *q, *k, *v, *ctx, *y, *h2, *ff;
    cudaGetSymbolAddress((void**)&h,   g_h);
    cudaGetSymbolAddress((void**)&q,   g_q);
    cudaGetSymbolAddress((void**)&k,   g_k);
    cudaGetSymbolAddress((void**)&v,   g_v);
    cudaGetSymbolAddress((void**)&ctx, g_ctx);
    cudaGetSymbolAddress((void**)&y,   g_y);
    cudaGetSymbolAddress((void**)&h2,  g_h2);
    cudaGetSymbolAddress((void**)&ff,  g_ff);

    const int flash_smem = (int)sizeof(FlashS);
    cudaFuncSetAttribute(flash_attn, cudaFuncAttributeMaxDynamicSharedMemorySize, flash_smem);
    cudaFuncSetAttribute(gemm_tc3<0,3>, cudaFuncAttributeMaxDynamicSharedMemorySize, GSMEM);
    cudaFuncSetAttribute(gemm_tc3<1,1>, cudaFuncAttributeMaxDynamicSharedMemorySize, GSMEM);
    cudaFuncSetAttribute(gemm_tc3<2,1>, cudaFuncAttributeMaxDynamicSharedMemorySize, GSMEM);

    // 1) h = rmsnorm(x, G1)
    rmsnorm_kernel<<<MTOK, 128>>>(X, G1, h);

    // 2) fused q/k/v = h @ W{q,k,v}^T  (NT, M=8192 N=512 K=512, z selects W)
    gemm_tc3<0,3><<<dim3(4,64,3), 256, GSMEM>>>(h, Wq, Wk, Wv, nullptr,
                                                q, k, v, DD, DD);

    // 3-5) fused attention: ctx = softmax(QK^T + bias) @ V  -> [B,S,D]
    flash_attn<<<dim3(SS/FQ, BB*HH), 256, flash_smem>>>(q, k, v, Bias, ctx);

    // 6) y = x + ctx @ Wo^T
    gemm_tc3<2,1><<<dim3(4,64), 256, GSMEM>>>(ctx, Wo, nullptr, nullptr, X,
                                              y, nullptr, nullptr, DD, DD);

    // 7) h2 = rmsnorm(y, G2)
    rmsnorm_kernel<<<MTOK, 128>>>(y, G2, h2);

    // 8) ff = relu(h2 @ Wi^T)   (M=8192 N=2048 K=512)
    gemm_tc3<1,1><<<dim3(16,64), 256, GSMEM>>>(h2, Wi, nullptr, nullptr, nullptr,
                                               ff, nullptr, nullptr, DD, DFF);

    // 9) out = y + ff @ Wo2^T   (M=8192 N=512 K=2048)
    gemm_tc3<2,1><<<dim3(4,64), 256, GSMEM>>>(ff, Wo2, nullptr, nullptr, y,
                                              Out, nullptr, nullptr, DFF, DD);
}

// round 7
// speedup vs baseline: 1.1068x; 1.1068x over previous
#include <cuda_runtime.h>
#include <cstdint>

// Shapes (compile-time constants)
#define BB 8
#define SS 1024
#define DD 512
#define HH 8
#define HD 64
#define DFF 2048
#define MTOK (BB*SS)   // 8192

typedef long long ll;

// ---------------- scratch (device globals: allocation-guard safe) -----------
__device__ float g_h  [MTOK*DD];        // rmsnorm1 output
__device__ float g_q  [MTOK*DD];
__device__ float g_k  [MTOK*DD];
__device__ float g_v  [MTOK*DD];
__device__ float g_ctx[MTOK*DD];
__device__ float g_y  [MTOK*DD];        // residual after attention
__device__ float g_h2 [MTOK*DD];        // rmsnorm2 output
__device__ float g_ff [MTOK*DFF];       // relu(ffn1)

// ---------------- helpers ----------------------------------------------------
__device__ __forceinline__ float ftf32(float x) {
    uint32_t o, i = __float_as_uint(x);
    asm("cvt.rna.tf32.f32 %0, %1;" : "=r"(o) : "r"(i));
    return __uint_as_float(o);
}
__device__ __forceinline__ void mma_tf32(float c[4], const uint32_t a[4], const uint32_t b[2]) {
    asm volatile(
        "mma.sync.aligned.m16n8k8.row.col.f32.tf32.tf32.f32 "
        "{%0,%1,%2,%3}, {%4,%5,%6,%7}, {%8,%9}, {%0,%1,%2,%3};\n"
        : "+f"(c[0]), "+f"(c[1]), "+f"(c[2]), "+f"(c[3])
        : "r"(a[0]), "r"(a[1]), "r"(a[2]), "r"(a[3]), "r"(b[0]), "r"(b[1]));
}

#define CP_ASYNC16(dst, src) \
    asm volatile("cp.async.cg.shared.global [%0], [%1], 16;\n" :: "r"(dst), "l"(src))
#define CP_COMMIT() asm volatile("cp.async.commit_group;\n" ::: "memory")
#define CP_WAIT(n)  asm volatile("cp.async.wait_group %0;\n" :: "n"(n) : "memory")

__device__ __forceinline__ uint32_t smem_u32(const void* p) {
    uint32_t a;
    asm("{ .reg .u64 t; cvta.to.shared.u64 t, %1; cvt.u32.u64 %0, t; }"
        : "=r"(a) : "l"(p));
    return a;
}

// ---------------- RMSNorm: one block (128 thr) per row of 512 ----------------
__global__ __launch_bounds__(128) void rmsnorm_kernel(
    const float* __restrict__ x, const float* __restrict__ w,
    float* __restrict__ out)
{
    const int row = blockIdx.x;
    const int t = threadIdx.x;
    const float4 v = ((const float4*)(x + (ll)row*DD))[t];
    float ss = v.x*v.x + v.y*v.y + v.z*v.z + v.w*v.w;
    #pragma unroll
    for (int o = 16; o; o >>= 1) ss += __shfl_xor_sync(0xFFFFFFFFu, ss, o);
    __shared__ float wsum[4];
    if ((t & 31) == 0) wsum[t >> 5] = ss;
    __syncthreads();
    const float tot = wsum[0] + wsum[1] + wsum[2] + wsum[3];
    const float r = rsqrtf(tot * (1.0f/DD) + 1e-6f);
    const float4 wv = ((const float4*)w)[t];
    float4 o4;
    o4.x = v.x * r * wv.x; o4.y = v.y * r * wv.y;
    o4.z = v.z * r * wv.z; o4.w = v.w * r * wv.w;
    ((float4*)(out + (ll)row*DD))[t] = o4;
}

// ---------------- TF32 mma.sync GEMM, 64x64 warp tiles, BK=32 ----------------
// C[m,n] = sum_k A[m,k]*B[n,k]  (both K-major / NT).
// 128x128 block, 128 threads (4 warps, 2x2), warp tile 64x64, BK=32,
// 3-stage cp.async pipeline with ONE __syncthreads per chunk,
// XOR-swizzled smem (no padding), raw-f32 operands (HW tf32 truncation).
// EPI: 0=none, 1=relu, 2=+Add.  NMAT=3: fused QKV (B/C via blockIdx.z).
#define STG   3
#define TILF  (128*32)              // floats per operand tile (16 KB)
#define STGF  (2*TILF)              // floats per stage
#define GSMEM (STG*STGF*4)          // 98304 B

// float index of (row r, col k) in a 128x32 XOR-swizzled tile
__device__ __forceinline__ int swz(int r, int k) {
    return r*32 + ((((k >> 2) ^ (r & 7)) << 2) | (k & 3));
}

template<int EPI, int NMAT>
__global__ __launch_bounds__(128, 2) void gemm_tc4(
    const float* __restrict__ A,
    const float* __restrict__ B0, const float* __restrict__ B1,
    const float* __restrict__ B2,
    const float* __restrict__ Add,
    float* __restrict__ C0, float* __restrict__ C1, float* __restrict__ C2,
    int K, int N)
{
    extern __shared__ float dsm[];

    const float* B = B0;
    float*       C = C0;
    if (NMAT == 3) {
        if (blockIdx.z == 1) { B = B1; C = C1; }
        else if (blockIdx.z == 2) { B = B2; C = C2; }
    }

    const int tid  = threadIdx.x;
    const int warp = tid >> 5, lane = tid & 31;
    const int wm   = warp >> 1, wn = warp & 1;      // 2x2 warp grid
    const int gid  = lane >> 2, tig = lane & 3;
    const int m0   = blockIdx.y * 128;
    const int n0   = blockIdx.x * 128;

    const uint32_t smb = smem_u32(dsm);
    const float* Ab = A + (ll)m0 * K;
    const float* Bb = B + (ll)n0 * K;

    float acc[4][8][4];
    #pragma unroll
    for (int mt = 0; mt < 4; ++mt)
        #pragma unroll
        for (int nt = 0; nt < 8; ++nt)
            #pragma unroll
            for (int i = 0; i < 4; ++i) acc[mt][nt][i] = 0.f;

    // stage chunk j (128 rows x 32 cols of A and B) into buffer j%STG
    auto issue = [&](int j) {
        const int st = j % STG;
        const int k0 = j * 32;
        const uint32_t ab = smb + st*STGF*4;
        const uint32_t bb = ab + TILF*4;
        #pragma unroll
        for (int i = 0; i < 8; ++i) {
            const int id = tid + i*128;
            const int r = id >> 3, c = id & 7;          // row, 16B-chunk
            const int sc = c ^ (r & 7);                 // swizzled chunk
            const uint32_t off = (r*32 + sc*4)*4;
            CP_ASYNC16(ab + off, Ab + (ll)r*K + k0 + c*4);
            CP_ASYNC16(bb + off, Bb + (ll)r*K + k0 + c*4);
        }
        CP_COMMIT();
    };

    const int NC = K / 32;      // >= 16 for all our GEMMs
    issue(0); issue(1);          // STG-1 = 2 chunks in flight

    for (int j = 0; j < NC; ++j) {
        CP_WAIT(STG-2);          // chunk j landed (this thread's groups)
        __syncthreads();         // all threads' parts + frees buf (j-1)%STG

        const float* As = dsm + (j % STG)*STGF;
        const float* Bs = As + TILF;

        #pragma unroll
        for (int ks = 0; ks < 4; ++ks) {
            const int k = ks*8 + tig;
            uint32_t af[4][4], bf[8][2];
            #pragma unroll
            for (int mt = 0; mt < 4; ++mt) {
                const int r = wm*64 + mt*16 + gid;
                af[mt][0] = __float_as_uint(As[swz(r,   k  )]);
                af[mt][1] = __float_as_uint(As[swz(r+8, k  )]);
                af[mt][2] = __float_as_uint(As[swz(r,   k+4)]);
                af[mt][3] = __float_as_uint(As[swz(r+8, k+4)]);
            }
            #pragma unroll
            for (int nt = 0; nt < 8; ++nt) {
                const int r = wn*64 + nt*8 + gid;
                bf[nt][0] = __float_as_uint(Bs[swz(r, k  )]);
                bf[nt][1] = __float_as_uint(Bs[swz(r, k+4)]);
            }
            #pragma unroll
            for (int mt = 0; mt < 4; ++mt)
                #pragma unroll
                for (int nt = 0; nt < 8; ++nt)
                    mma_tf32(acc[mt][nt], af[mt], bf[nt]);
        }

        if (j + STG - 1 < NC) issue(j + STG - 1);   // writes buf (j-1)%STG
    }

    // ---- epilogue
    #pragma unroll
    for (int mt = 0; mt < 4; ++mt) {
        #pragma unroll
        for (int nt = 0; nt < 8; ++nt) {
            const int col = n0 + wn*64 + nt*8 + tig*2;
            #pragma unroll
            for (int h = 0; h < 2; ++h) {
                const ll row = (ll)(m0 + wm*64 + mt*16 + gid + h*8);
                float2 v;
                v.x = acc[mt][nt][h*2+0];
                v.y = acc[mt][nt][h*2+1];
                if (EPI == 1) { v.x = fmaxf(v.x, 0.f); v.y = fmaxf(v.y, 0.f); }
                if (EPI == 2) {
                    const float2 ad = *(const float2*)(Add + row*N + col);
                    v.x += ad.x; v.y += ad.y;
                }
                *(float2*)(C + row*N + col) = v;
            }
        }
    }
}

// ---------------- Fused flash attention (unchanged, passing) -----------------
#define FQ 128
#define FK 64
#define FLDS 68   // 64 + 4 pad

struct FlashS {
    float stage[FQ][FLDS];
    float ks[FK][FLDS];
    float vs[HD][FLDS];
};

__global__ __launch_bounds__(256) void flash_attn(
    const float* __restrict__ Q, const float* __restrict__ Kg,
    const float* __restrict__ Vg, const float* __restrict__ Bias,
    float* __restrict__ Ctx)
{
    extern __shared__ char smraw[];
    FlashS& sm = *reinterpret_cast<FlashS*>(smraw);

    const int z  = blockIdx.y;
    const int b  = z >> 3, hh = z & 7;
    const int q0 = blockIdx.x * FQ;
    const ll off = (ll)b*SS*DD + (ll)hh*HD;
    const float* Qz = Q  + off;
    const float* Kz = Kg + off;
    const float* Vz = Vg + off;
    const float* Bz = Bias + ((ll)z*SS + q0)*SS;
    float*       Cz = Ctx + off;

    const int tid = threadIdx.x, warp = tid >> 5, lane = tid & 31;
    const int gid = lane >> 2, tig = lane & 3;
    const int wrow = warp * 16;

    #pragma unroll
    for (int i = 0; i < 8; ++i) {
        const int idx = tid + i*256;
        const int r = idx >> 4, c = (idx & 15) << 2;
        float4 v = *(const float4*)(Qz + (ll)(q0 + r)*DD + c);
        v.x = ftf32(v.x); v.y = ftf32(v.y); v.z = ftf32(v.z); v.w = ftf32(v.w);
        *(float4*)&sm.stage[r][c] = v;
    }
    __syncthreads();
    uint32_t qf[8][4];
    #pragma unroll
    for (int kc = 0; kc < 8; ++kc) {
        const int k = kc*8 + tig;
        qf[kc][0] = __float_as_uint(sm.stage[wrow+gid  ][k  ]);
        qf[kc][1] = __float_as_uint(sm.stage[wrow+gid+8][k  ]);
        qf[kc][2] = __float_as_uint(sm.stage[wrow+gid  ][k+4]);
        qf[kc][3] = __float_as_uint(sm.stage[wrow+gid+8][k+4]);
    }
    __syncthreads();

    float oacc[8][4];
    #pragma unroll
    for (int nt = 0; nt < 8; ++nt)
        #pragma unroll
        for (int i = 0; i < 4; ++i) oacc[nt][i] = 0.f;
    float m0v = -1e30f, m1v = -1e30f, l0 = 0.f, l1 = 0.f;

    for (int j = 0; j < SS/FK; ++j) {
        #pragma unroll
        for (int i = 0; i < 4; ++i) {
            const int idx = tid + i*256;
            const int r = idx >> 4, c = (idx & 15) << 2;
            float4 kv = *(const float4*)(Kz + (ll)(j*FK + r)*DD + c);
            kv.x = ftf32(kv.x); kv.y = ftf32(kv.y); kv.z = ftf32(kv.z); kv.w = ftf32(kv.w);
            *(float4*)&sm.ks[r][c] = kv;
            float4 vv = *(const float4*)(Vz + (ll)(j*FK + r)*DD + c);
            vv.x = ftf32(vv.x); vv.y = ftf32(vv.y); vv.z = ftf32(vv.z); vv.w = ftf32(vv.w);
            sm.vs[c+0][r] = vv.x; sm.vs[c+1][r] = vv.y;
            sm.vs[c+2][r] = vv.z; sm.vs[c+3][r] = vv.w;
        }
        __syncthreads();

        float sacc[8][4];
        #pragma unroll
        for (int nt = 0; nt < 8; ++nt)
            #pragma unroll
            for (int i = 0; i < 4; ++i) sacc[nt][i] = 0.f;
        #pragma unroll
        for (int kc = 0; kc < 8; ++kc) {
            const int k = kc*8 + tig;
            #pragma unroll
            for (int nt = 0; nt < 8; ++nt) {
                const int cc = nt*8 + gid;
                uint32_t bf[2];
                bf[0] = __float_as_uint(sm.ks[cc][k  ]);
                bf[1] = __float_as_uint(sm.ks[cc][k+4]);
                mma_tf32(sacc[nt], qf[kc], bf);
            }
        }

        float mx0 = -1e30f, mx1 = -1e30f;
        const float* br0 = Bz + (ll)(wrow+gid  )*SS + j*FK + 2*tig;
        const float* br1 = Bz + (ll)(wrow+gid+8)*SS + j*FK + 2*tig;
        #pragma unroll
        for (int nt = 0; nt < 8; ++nt) {
            const float2 b0 = *(const float2*)(br0 + nt*8);
            const float2 b1 = *(const float2*)(br1 + nt*8);
            sacc[nt][0] += b0.x; sacc[nt][1] += b0.y;
            sacc[nt][2] += b1.x; sacc[nt][3] += b1.y;
            mx0 = fmaxf(mx0, fmaxf(sacc[nt][0], sacc[nt][1]));
            mx1 = fmaxf(mx1, fmaxf(sacc[nt][2], sacc[nt][3]));
        }
        #pragma unroll
        for (int o = 1; o <= 2; o <<= 1) {
            mx0 = fmaxf(mx0, __shfl_xor_sync(0xFFFFFFFFu, mx0, o));
            mx1 = fmaxf(mx1, __shfl_xor_sync(0xFFFFFFFFu, mx1, o));
        }
        const float mn0 = fmaxf(m0v, mx0), mn1 = fmaxf(m1v, mx1);
        const float sc0 = __expf(m0v - mn0), sc1 = __expf(m1v - mn1);
        m0v = mn0; m1v = mn1;

        float rs0 = 0.f, rs1 = 0.f;
        #pragma unroll
        for (int nt = 0; nt < 8; ++nt) {
            const float p0 = __expf(sacc[nt][0] - mn0);
            const float p1 = __expf(sacc[nt][1] - mn0);
            const float p2 = __expf(sacc[nt][2] - mn1);
            const float p3 = __expf(sacc[nt][3] - mn1);
            rs0 += p0 + p1; rs1 += p2 + p3;
            float2 w0; w0.x = ftf32(p0); w0.y = ftf32(p1);
            float2 w1; w1.x = ftf32(p2); w1.y = ftf32(p3);
            *(float2*)&sm.stage[wrow+gid  ][nt*8 + 2*tig] = w0;
            *(float2*)&sm.stage[wrow+gid+8][nt*8 + 2*tig] = w1;
        }
        #pragma unroll
        for (int o = 1; o <= 2; o <<= 1) {
            rs0 += __shfl_xor_sync(0xFFFFFFFFu, rs0, o);
            rs1 += __shfl_xor_sync(0xFFFFFFFFu, rs1, o);
        }
        l0 = l0*sc0 + rs0;
        l1 = l1*sc1 + rs1;
        #pragma unroll
        for (int nt = 0; nt < 8; ++nt) {
            oacc[nt][0] *= sc0; oacc[nt][1] *= sc0;
            oacc[nt][2] *= sc1; oacc[nt][3] *= sc1;
        }
        __syncwarp();

        #pragma unroll
        for (int kc = 0; kc < 8; ++kc) {
            const int k = kc*8 + tig;
            uint32_t af[4];
            af[0] = __float_as_uint(sm.stage[wrow+gid  ][k  ]);
            af[1] = __float_as_uint(sm.stage[wrow+gid+8][k  ]);
            af[2] = __float_as_uint(sm.stage[wrow+gid  ][k+4]);
            af[3] = __float_as_uint(sm.stage[wrow+gid+8][k+4]);
            #pragma unroll
            for (int nt = 0; nt < 8; ++nt) {
                const int cc = nt*8 + gid;
                uint32_t bf[2];
                bf[0] = __float_as_uint(sm.vs[cc][k  ]);
                bf[1] = __float_as_uint(sm.vs[cc][k+4]);
                mma_tf32(oacc[nt], af, bf);
            }
        }
        __syncthreads();
    }

    const float inv0 = 1.f / l0, inv1 = 1.f / l1;
    #pragma unroll
    for (int nt = 0; nt < 8; ++nt) {
        const int col = nt*8 + 2*tig;
        float2 w0; w0.x = oacc[nt][0]*inv0; w0.y = oacc[nt][1]*inv0;
        float2 w1; w1.x = oacc[nt][2]*inv1; w1.y = oacc[nt][3]*inv1;
        *(float2*)(Cz + (ll)(q0 + wrow + gid    )*DD + col) = w0;
        *(float2*)(Cz + (ll)(q0 + wrow + gid + 8)*DD + col) = w1;
    }
}

// ---------------- host orchestration -----------------------------------------
extern "C" void kernel_launch(void* const* d_in, const int* in_sizes, int n_in,
                              void* d_out, int out_size)
{
    const float* Wk   = (const float*)d_in[0]; // primals_1
    const float* Wo   = (const float*)d_in[1]; // primals_2
    const float* Wq   = (const float*)d_in[2]; // primals_3
    const float* Wv   = (const float*)d_in[3]; // primals_4
    const float* G1   = (const float*)d_in[4]; // primals_5
    const float* Wi   = (const float*)d_in[5]; // primals_6 [DFF,D]
    const float* Wo2  = (const float*)d_in[6]; // primals_7 [D,DFF]
    const float* G2   = (const float*)d_in[7]; // primals_8
    const float* X    = (const float*)d_in[8]; // primals_9 [B,S,D]
    const float* Bias = (const float*)d_in[9]; // primals_10 [B,H,S,S]
    float* Out = (float*)d_out;

    float *h, *q, *k, *v, *ctx, *y, *h2, *ff;
    cudaGetSymbolAddress((void**)&h,   g_h);
    cudaGetSymbolAddress((void**)&q,   g_q);
    cudaGetSymbolAddress((void**)&k,   g_k);
    cudaGetSymbolAddress((void**)&v,   g_v);
    cudaGetSymbolAddress((void**)&ctx, g_ctx);
    cudaGetSymbolAddress((void**)&y,   g_y);
    cudaGetSymbolAddress((void**)&h2,  g_h2);
    cudaGetSymbolAddress((void**)&ff,  g_ff);

    const int flash_smem = (int)sizeof(FlashS);
    cudaFuncSetAttribute(flash_attn, cudaFuncAttributeMaxDynamicSharedMemorySize, flash_smem);
    cudaFuncSetAttribute(gemm_tc4<0,3>, cudaFuncAttributeMaxDynamicSharedMemorySize, GSMEM);
    cudaFuncSetAttribute(gemm_tc4<1,1>, cudaFuncAttributeMaxDynamicSharedMemorySize, GSMEM);
    cudaFuncSetAttribute(gemm_tc4<2,1>, cudaFuncAttributeMaxDynamicSharedMemorySize, GSMEM);

    // 1) h = rmsnorm(x, G1)
    rmsnorm_kernel<<<MTOK, 128>>>(X, G1, h);

    // 2) fused q/k/v = h @ W{q,k,v}^T  (NT, M=8192 N=512 K=512, z selects W)
    gemm_tc4<0,3><<<dim3(4,64,3), 128, GSMEM>>>(h, Wq, Wk, Wv, nullptr,
                                                q, k, v, DD, DD);

    // 3-5) fused attention: ctx = softmax(QK^T + bias) @ V  -> [B,S,D]
    flash_attn<<<dim3(SS/FQ, BB*HH), 256, flash_smem>>>(q, k, v, Bias, ctx);

    // 6) y = x + ctx @ Wo^T
    gemm_tc4<2,1><<<dim3(4,64), 128, GSMEM>>>(ctx, Wo, nullptr, nullptr, X,
                                              y, nullptr, nullptr, DD, DD);

    // 7) h2 = rmsnorm(y, G2)
    rmsnorm_kernel<<<MTOK, 128>>>(y, G2, h2);

    // 8) ff = relu(h2 @ Wi^T)   (M=8192 N=2048 K=512)
    gemm_tc4<1,1><<<dim3(16,64), 128, GSMEM>>>(h2, Wi, nullptr, nullptr, nullptr,
                                               ff, nullptr, nullptr, DD, DFF);

    // 9) out = y + ff @ Wo2^T   (M=8192 N=512 K=2048)
    gemm_tc4<2,1><<<dim3(4,64), 128, GSMEM>>>(ff, Wo2, nullptr, nullptr, y,
                                              Out, nullptr, nullptr, DFF, DD);
}

// round 8
// speedup vs baseline: 1.1264x; 1.0177x over previous
#include <cuda_runtime.h>
#include <cstdint>

// Shapes (compile-time constants)
#define BB 8
#define SS 1024
#define DD 512
#define HH 8
#define HD 64
#define DFF 2048
#define MTOK (BB*SS)   // 8192

typedef long long ll;

// ---------------- scratch (device globals: allocation-guard safe) -----------
__device__ float g_h  [MTOK*DD];        // rmsnorm1 output
__device__ float g_q  [MTOK*DD];
__device__ float g_k  [MTOK*DD];
__device__ float g_v  [MTOK*DD];
__device__ float g_ctx[MTOK*DD];
__device__ float g_y  [MTOK*DD];        // residual after attention
__device__ float g_h2 [MTOK*DD];        // rmsnorm2 output
__device__ float g_ff [MTOK*DFF];       // relu(ffn1)

// ---------------- helpers ----------------------------------------------------
__device__ __forceinline__ float ftf32(float x) {
    uint32_t o, i = __float_as_uint(x);
    asm("cvt.rna.tf32.f32 %0, %1;" : "=r"(o) : "r"(i));
    return __uint_as_float(o);
}
__device__ __forceinline__ void mma_tf32(float c[4], const uint32_t a[4], const uint32_t b[2]) {
    asm volatile(
        "mma.sync.aligned.m16n8k8.row.col.f32.tf32.tf32.f32 "
        "{%0,%1,%2,%3}, {%4,%5,%6,%7}, {%8,%9}, {%0,%1,%2,%3};\n"
        : "+f"(c[0]), "+f"(c[1]), "+f"(c[2]), "+f"(c[3])
        : "r"(a[0]), "r"(a[1]), "r"(a[2]), "r"(a[3]), "r"(b[0]), "r"(b[1]));
}

#define LDSM4(r0,r1,r2,r3,addr) \
    asm volatile("ldmatrix.sync.aligned.m8n8.x4.shared.b16 {%0,%1,%2,%3}, [%4];" \
        : "=r"(r0), "=r"(r1), "=r"(r2), "=r"(r3) : "r"(addr))

#define CP_ASYNC16(dst, src) \
    asm volatile("cp.async.cg.shared.global [%0], [%1], 16;\n" :: "r"(dst), "l"(src))
#define CP_COMMIT() asm volatile("cp.async.commit_group;\n" ::: "memory")
#define CP_WAIT(n)  asm volatile("cp.async.wait_group %0;\n" :: "n"(n) : "memory")

__device__ __forceinline__ uint32_t smem_u32(const void* p) {
    uint32_t a;
    asm("{ .reg .u64 t; cvta.to.shared.u64 t, %1; cvt.u32.u64 %0, t; }"
        : "=r"(a) : "l"(p));
    return a;
}

// ---------------- RMSNorm: one block (128 thr) per row of 512 ----------------
__global__ __launch_bounds__(128) void rmsnorm_kernel(
    const float* __restrict__ x, const float* __restrict__ w,
    float* __restrict__ out)
{
    const int row = blockIdx.x;
    const int t = threadIdx.x;
    const float4 v = ((const float4*)(x + (ll)row*DD))[t];
    float ss = v.x*v.x + v.y*v.y + v.z*v.z + v.w*v.w;
    #pragma unroll
    for (int o = 16; o; o >>= 1) ss += __shfl_xor_sync(0xFFFFFFFFu, ss, o);
    __shared__ float wsum[4];
    if ((t & 31) == 0) wsum[t >> 5] = ss;
    __syncthreads();
    const float tot = wsum[0] + wsum[1] + wsum[2] + wsum[3];
    const float r = rsqrtf(tot * (1.0f/DD) + 1e-6f);
    const float4 wv = ((const float4*)w)[t];
    float4 o4;
    o4.x = v.x * r * wv.x; o4.y = v.y * r * wv.y;
    o4.z = v.z * r * wv.z; o4.w = v.w * r * wv.w;
    ((float4*)(out + (ll)row*DD))[t] = o4;
}

// ---------------- TF32 mma.sync GEMM, ldmatrix fragments ---------------------
// C[m,n] = sum_k A[m,k]*B[n,k]  (both K-major / NT).
// 128x128 block, 128 threads (4 warps, 2x2), warp tile 64x64, BK=32,
// 3-stage cp.async pipeline (one barrier per chunk), XOR-swizzled smem,
// ldmatrix.x4 fragment loads, raw-f32 operands (HW tf32 truncation).
// EPI: 0=none, 1=relu, 2=+Add.  NMAT=3: fused QKV (B/C via blockIdx.z).
#define STG   3
#define TILF  (128*32)              // floats per operand tile (16 KB)
#define STGF  (2*TILF)              // floats per stage
#define GSMEM (STG*STGF*4)          // 98304 B

template<int EPI, int NMAT>
__global__ __launch_bounds__(128, 2) void gemm_tc5(
    const float* __restrict__ A,
    const float* __restrict__ B0, const float* __restrict__ B1,
    const float* __restrict__ B2,
    const float* __restrict__ Add,
    float* __restrict__ C0, float* __restrict__ C1, float* __restrict__ C2,
    int K, int N)
{
    extern __shared__ float dsm[];

    const float* B = B0;
    float*       C = C0;
    if (NMAT == 3) {
        if (blockIdx.z == 1) { B = B1; C = C1; }
        else if (blockIdx.z == 2) { B = B2; C = C2; }
    }

    const int tid  = threadIdx.x;
    const int warp = tid >> 5, lane = tid & 31;
    const int wm   = warp >> 1, wn = warp & 1;      // 2x2 warp grid
    const int gid  = lane >> 2, tig = lane & 3;
    const int m0   = blockIdx.y * 128;
    const int n0   = blockIdx.x * 128;

    const uint32_t smb = smem_u32(dsm);
    const float* Ab = A + (ll)m0 * K;
    const float* Bb = B + (ll)n0 * K;

    // ldmatrix per-thread row mapping: quad q supplies rows of sub-matrix q
    const int quad = lane >> 3;
    const int rl   = lane & 7;
    const int lrow = ((quad & 1) << 3) | rl;  // row offset within 16-row block
    const int lchk = quad >> 1;               // 16B-chunk offset (0/1)

    uint32_t abase[4], akey[4], bbase[4], bkey[4];
    #pragma unroll
    for (int mt = 0; mt < 4; ++mt) {
        const int r = wm*64 + mt*16 + lrow;
        abase[mt] = (uint32_t)r * 128u;       // byte offset of row in tile
        akey[mt]  = (uint32_t)(r & 7);
    }
    #pragma unroll
    for (int p = 0; p < 4; ++p) {
        const int r = wn*64 + p*16 + lrow;
        bbase[p] = (uint32_t)r * 128u;
        bkey[p]  = (uint32_t)(r & 7);
    }

    float acc[4][8][4];
    #pragma unroll
    for (int mt = 0; mt < 4; ++mt)
        #pragma unroll
        for (int nt = 0; nt < 8; ++nt)
            #pragma unroll
            for (int i = 0; i < 4; ++i) acc[mt][nt][i] = 0.f;

    // stage chunk j (128 rows x 32 cols of A and B) into buffer j%STG
    auto issue = [&](int j) {
        const int st = j % STG;
        const int k0 = j * 32;
        const uint32_t ab = smb + st*STGF*4;
        const uint32_t bb = ab + TILF*4;
        #pragma unroll
        for (int i = 0; i < 8; ++i) {
            const int id = tid + i*128;
            const int r = id >> 3, c = id & 7;          // row, 16B-chunk
            const int sc = c ^ (r & 7);                 // swizzled chunk
            const uint32_t off = (r*32 + sc*4)*4;
            CP_ASYNC16(ab + off, Ab + (ll)r*K + k0 + c*4);
            CP_ASYNC16(bb + off, Bb + (ll)r*K + k0 + c*4);
        }
        CP_COMMIT();
    };

    const int NC = K / 32;
    issue(0); issue(1);

    for (int j = 0; j < NC; ++j) {
        CP_WAIT(STG-2);
        __syncthreads();

        const uint32_t asmb = smb + (j % STG)*STGF*4;
        const uint32_t bsmb = asmb + TILF*4;

        #pragma unroll
        for (int ks = 0; ks < 4; ++ks) {
            const uint32_t chunk = 2u*ks + lchk;
            uint32_t af[4][4], bq[4][4];
            #pragma unroll
            for (int mt = 0; mt < 4; ++mt) {
                const uint32_t addr = asmb + abase[mt] + ((chunk ^ akey[mt]) << 4);
                LDSM4(af[mt][0], af[mt][1], af[mt][2], af[mt][3], addr);
            }
            #pragma unroll
            for (int p = 0; p < 4; ++p) {
                const uint32_t addr = bsmb + bbase[p] + ((chunk ^ bkey[p]) << 4);
                LDSM4(bq[p][0], bq[p][1], bq[p][2], bq[p][3], addr);
            }
            #pragma unroll
            for (int mt = 0; mt < 4; ++mt)
                #pragma unroll
                for (int nt = 0; nt < 8; ++nt) {
                    const int p = nt >> 1, o = nt & 1;
                    uint32_t b2[2] = { bq[p][o], bq[p][o+2] };
                    mma_tf32(acc[mt][nt], af[mt], b2);
                }
        }

        if (j + STG - 1 < NC) issue(j + STG - 1);
    }

    // ---- epilogue
    #pragma unroll
    for (int mt = 0; mt < 4; ++mt) {
        #pragma unroll
        for (int nt = 0; nt < 8; ++nt) {
            const int col = n0 + wn*64 + nt*8 + tig*2;
            #pragma unroll
            for (int h = 0; h < 2; ++h) {
                const ll row = (ll)(m0 + wm*64 + mt*16 + gid + h*8);
                float2 v;
                v.x = acc[mt][nt][h*2+0];
                v.y = acc[mt][nt][h*2+1];
                if (EPI == 1) { v.x = fmaxf(v.x, 0.f); v.y = fmaxf(v.y, 0.f); }
                if (EPI == 2) {
                    const float2 ad = *(const float2*)(Add + row*N + col);
                    v.x += ad.x; v.y += ad.y;
                }
                *(float2*)(C + row*N + col) = v;
            }
        }
    }
}

// ---------------- Fused flash attention (unchanged, passing) -----------------
#define FQ 128
#define FK 64
#define FLDS 68   // 64 + 4 pad

struct FlashS {
    float stage[FQ][FLDS];
    float ks[FK][FLDS];
    float vs[HD][FLDS];
};

__global__ __launch_bounds__(256) void flash_attn(
    const float* __restrict__ Q, const float* __restrict__ Kg,
    const float* __restrict__ Vg, const float* __restrict__ Bias,
    float* __restrict__ Ctx)
{
    extern __shared__ char smraw[];
    FlashS& sm = *reinterpret_cast<FlashS*>(smraw);

    const int z  = blockIdx.y;
    const int b  = z >> 3, hh = z & 7;
    const int q0 = blockIdx.x * FQ;
    const ll off = (ll)b*SS*DD + (ll)hh*HD;
    const float* Qz = Q  + off;
    const float* Kz = Kg + off;
    const float* Vz = Vg + off;
    const float* Bz = Bias + ((ll)z*SS + q0)*SS;
    float*       Cz = Ctx + off;

    const int tid = threadIdx.x, warp = tid >> 5, lane = tid & 31;
    const int gid = lane >> 2, tig = lane & 3;
    const int wrow = warp * 16;

    #pragma unroll
    for (int i = 0; i < 8; ++i) {
        const int idx = tid + i*256;
        const int r = idx >> 4, c = (idx & 15) << 2;
        float4 v = *(const float4*)(Qz + (ll)(q0 + r)*DD + c);
        v.x = ftf32(v.x); v.y = ftf32(v.y); v.z = ftf32(v.z); v.w = ftf32(v.w);
        *(float4*)&sm.stage[r][c] = v;
    }
    __syncthreads();
    uint32_t qf[8][4];
    #pragma unroll
    for (int kc = 0; kc < 8; ++kc) {
        const int k = kc*8 + tig;
        qf[kc][0] = __float_as_uint(sm.stage[wrow+gid  ][k  ]);
        qf[kc][1] = __float_as_uint(sm.stage[wrow+gid+8][k  ]);
        qf[kc][2] = __float_as_uint(sm.stage[wrow+gid  ][k+4]);
        qf[kc][3] = __float_as_uint(sm.stage[wrow+gid+8][k+4]);
    }
    __syncthreads();

    float oacc[8][4];
    #pragma unroll
    for (int nt = 0; nt < 8; ++nt)
        #pragma unroll
        for (int i = 0; i < 4; ++i) oacc[nt][i] = 0.f;
    float m0v = -1e30f, m1v = -1e30f, l0 = 0.f, l1 = 0.f;

    for (int j = 0; j < SS/FK; ++j) {
        #pragma unroll
        for (int i = 0; i < 4; ++i) {
            const int idx = tid + i*256;
            const int r = idx >> 4, c = (idx & 15) << 2;
            float4 kv = *(const float4*)(Kz + (ll)(j*FK + r)*DD + c);
            kv.x = ftf32(kv.x); kv.y = ftf32(kv.y); kv.z = ftf32(kv.z); kv.w = ftf32(kv.w);
            *(float4*)&sm.ks[r][c] = kv;
            float4 vv = *(const float4*)(Vz + (ll)(j*FK + r)*DD + c);
            vv.x = ftf32(vv.x); vv.y = ftf32(vv.y); vv.z = ftf32(vv.z); vv.w = ftf32(vv.w);
            sm.vs[c+0][r] = vv.x; sm.vs[c+1][r] = vv.y;
            sm.vs[c+2][r] = vv.z; sm.vs[c+3][r] = vv.w;
        }
        __syncthreads();

        float sacc[8][4];
        #pragma unroll
        for (int nt = 0; nt < 8; ++nt)
            #pragma unroll
            for (int i = 0; i < 4; ++i) sacc[nt][i] = 0.f;
        #pragma unroll
        for (int kc = 0; kc < 8; ++kc) {
            const int k = kc*8 + tig;
            #pragma unroll
            for (int nt = 0; nt < 8; ++nt) {
                const int cc = nt*8 + gid;
                uint32_t bf[2];
                bf[0] = __float_as_uint(sm.ks[cc][k  ]);
                bf[1] = __float_as_uint(sm.ks[cc][k+4]);
                mma_tf32(sacc[nt], qf[kc], bf);
            }
        }

        float mx0 = -1e30f, mx1 = -1e30f;
        const float* br0 = Bz + (ll)(wrow+gid  )*SS + j*FK + 2*tig;
        const float* br1 = Bz + (ll)(wrow+gid+8)*SS + j*FK + 2*tig;
        #pragma unroll
        for (int nt = 0; nt < 8; ++nt) {
            const float2 b0 = *(const float2*)(br0 + nt*8);
            const float2 b1 = *(const float2*)(br1 + nt*8);
            sacc[nt][0] += b0.x; sacc[nt][1] += b0.y;
            sacc[nt][2] += b1.x; sacc[nt][3] += b1.y;
            mx0 = fmaxf(mx0, fmaxf(sacc[nt][0], sacc[nt][1]));
            mx1 = fmaxf(mx1, fmaxf(sacc[nt][2], sacc[nt][3]));
        }
        #pragma unroll
        for (int o = 1; o <= 2; o <<= 1) {
            mx0 = fmaxf(mx0, __shfl_xor_sync(0xFFFFFFFFu, mx0, o));
            mx1 = fmaxf(mx1, __shfl_xor_sync(0xFFFFFFFFu, mx1, o));
        }
        const float mn0 = fmaxf(m0v, mx0), mn1 = fmaxf(m1v, mx1);
        const float sc0 = __expf(m0v - mn0), sc1 = __expf(m1v - mn1);
        m0v = mn0; m1v = mn1;

        float rs0 = 0.f, rs1 = 0.f;
        #pragma unroll
        for (int nt = 0; nt < 8; ++nt) {
            const float p0 = __expf(sacc[nt][0] - mn0);
            const float p1 = __expf(sacc[nt][1] - mn0);
            const float p2 = __expf(sacc[nt][2] - mn1);
            const float p3 = __expf(sacc[nt][3] - mn1);
            rs0 += p0 + p1; rs1 += p2 + p3;
            float2 w0; w0.x = ftf32(p0); w0.y = ftf32(p1);
            float2 w1; w1.x = ftf32(p2); w1.y = ftf32(p3);
            *(float2*)&sm.stage[wrow+gid  ][nt*8 + 2*tig] = w0;
            *(float2*)&sm.stage[wrow+gid+8][nt*8 + 2*tig] = w1;
        }
        #pragma unroll
        for (int o = 1; o <= 2; o <<= 1) {
            rs0 += __shfl_xor_sync(0xFFFFFFFFu, rs0, o);
            rs1 += __shfl_xor_sync(0xFFFFFFFFu, rs1, o);
        }
        l0 = l0*sc0 + rs0;
        l1 = l1*sc1 + rs1;
        #pragma unroll
        for (int nt = 0; nt < 8; ++nt) {
            oacc[nt][0] *= sc0; oacc[nt][1] *= sc0;
            oacc[nt][2] *= sc1; oacc[nt][3] *= sc1;
        }
        __syncwarp();

        #pragma unroll
        for (int kc = 0; kc < 8; ++kc) {
            const int k = kc*8 + tig;
            uint32_t af[4];
            af[0] = __float_as_uint(sm.stage[wrow+gid  ][k  ]);
            af[1] = __float_as_uint(sm.stage[wrow+gid+8][k  ]);
            af[2] = __float_as_uint(sm.stage[wrow+gid  ][k+4]);
            af[3] = __float_as_uint(sm.stage[wrow+gid+8][k+4]);
            #pragma unroll
            for (int nt = 0; nt < 8; ++nt) {
                const int cc = nt*8 + gid;
                uint32_t bf[2];
                bf[0] = __float_as_uint(sm.vs[cc][k  ]);
                bf[1] = __float_as_uint(sm.vs[cc][k+4]);
                mma_tf32(oacc[nt], af, bf);
            }
        }
        __syncthreads();
    }

    const float inv0 = 1.f / l0, inv1 = 1.f / l1;
    #pragma unroll
    for (int nt = 0; nt < 8; ++nt) {
        const int col = nt*8 + 2*tig;
        float2 w0; w0.x = oacc[nt][0]*inv0; w0.y = oacc[nt][1]*inv0;
        float2 w1; w1.x = oacc[nt][2]*inv1; w1.y = oacc[nt][3]*inv1;
        *(float2*)(Cz + (ll)(q0 + wrow + gid    )*DD + col) = w0;
        *(float2*)(Cz + (ll)(q0 + wrow + gid + 8)*DD + col) = w1;
    }
}

// ---------------- host orchestration -----------------------------------------
extern "C" void kernel_launch(void* const* d_in, const int* in_sizes, int n_in,
                              void* d_out, int out_size)
{
    const float* Wk   = (const float*)d_in[0]; // primals_1
    const float* Wo   = (const float*)d_in[1]; // primals_2
    const float* Wq   = (const float*)d_in[2]; // primals_3
    const float* Wv   = (const float*)d_in[3]; // primals_4
    const float* G1   = (const float*)d_in[4]; // primals_5
    const float* Wi   = (const float*)d_in[5]; // primals_6 [DFF,D]
    const float* Wo2  = (const float*)d_in[6]; // primals_7 [D,DFF]
    const float* G2   = (const float*)d_in[7]; // primals_8
    const float* X    = (const float*)d_in[8]; // primals_9 [B,S,D]
    const float* Bias = (const float*)d_in[9]; // primals_10 [B,H,S,S]
    float* Out = (float*)d_out;

    float *h, *q, *k, *v, *ctx, *y, *h2, *ff;
    cudaGetSymbolAddress((void**)&h,   g_h);
    cudaGetSymbolAddress((void**)&q,   g_q);
    cudaGetSymbolAddress((void**)&k,   g_k);
    cudaGetSymbolAddress((void**)&v,   g_v);
    cudaGetSymbolAddress((void**)&ctx, g_ctx);
    cudaGetSymbolAddress((void**)&y,   g_y);
    cudaGetSymbolAddress((void**)&h2,  g_h2);
    cudaGetSymbolAddress((void**)&ff,  g_ff);

    const int flash_smem = (int)sizeof(FlashS);
    cudaFuncSetAttribute(flash_attn, cudaFuncAttributeMaxDynamicSharedMemorySize, flash_smem);
    cudaFuncSetAttribute(gemm_tc5<0,3>, cudaFuncAttributeMaxDynamicSharedMemorySize, GSMEM);
    cudaFuncSetAttribute(gemm_tc5<1,1>, cudaFuncAttributeMaxDynamicSharedMemorySize, GSMEM);
    cudaFuncSetAttribute(gemm_tc5<2,1>, cudaFuncAttributeMaxDynamicSharedMemorySize, GSMEM);

    // 1) h = rmsnorm(x, G1)
    rmsnorm_kernel<<<MTOK, 128>>>(X, G1, h);

    // 2) fused q/k/v = h @ W{q,k,v}^T  (NT, M=8192 N=512 K=512, z selects W)
    gemm_tc5<0,3><<<dim3(4,64,3), 128, GSMEM>>>(h, Wq, Wk, Wv, nullptr,
                                                q, k, v, DD, DD);

    // 3-5) fused attention: ctx = softmax(QK^T + bias) @ V  -> [B,S,D]
    flash_attn<<<dim3(SS/FQ, BB*HH), 256, flash_smem>>>(q, k, v, Bias, ctx);

    // 6) y = x + ctx @ Wo^T
    gemm_tc5<2,1><<<dim3(4,64), 128, GSMEM>>>(ctx, Wo, nullptr, nullptr, X,
                                              y, nullptr, nullptr, DD, DD);

    // 7) h2 = rmsnorm(y, G2)
    rmsnorm_kernel<<<MTOK, 128>>>(y, G2, h2);

    // 8) ff = relu(h2 @ Wi^T)   (M=8192 N=2048 K=512)
    gemm_tc5<1,1><<<dim3(16,64), 128, GSMEM>>>(h2, Wi, nullptr, nullptr, nullptr,
                                               ff, nullptr, nullptr, DD, DFF);

    // 9) out = y + ff @ Wo2^T   (M=8192 N=512 K=2048)
    gemm_tc5<2,1><<<dim3(4,64), 128, GSMEM>>>(ff, Wo2, nullptr, nullptr, y,
                                              Out, nullptr, nullptr, DFF, DD);
}